// round 6
// baseline (speedup 1.0000x reference)
#include <cuda_runtime.h>
#include <math.h>

#define Bsz 8
#define Tt 12
#define Hh 256
#define Ww 256
#define EC 8
#define HC 16
#define HW (Hh*Ww)

// Scratch (device globals; no allocations allowed)
__device__ float g_e1 [Bsz*Tt*EC*HW];   // encoder conv1 output (96 frames x 8ch)
__device__ float g_enc[Bsz*Tt*EC*HW];   // encoder conv2 output
__device__ float g_h[2][Bsz*HC*HW];     // ping-pong hidden state
__device__ float g_c[2][Bsz*HC*HW];     // ping-pong cell state

__device__ __forceinline__ float sigmf(float x){ return 1.0f/(1.0f+expf(-x)); }

// ---- packed f32x2 helpers (sm_100+) ----
__device__ __forceinline__ void fma2(unsigned long long& acc,
                                     unsigned long long a,
                                     unsigned long long b){
    asm("fma.rn.f32x2 %0, %1, %2, %3;" : "=l"(acc) : "l"(a), "l"(b), "l"(acc));
}
__device__ __forceinline__ void unpack2(unsigned long long v, float& lo, float& hi){
    asm("mov.b64 {%0, %1}, %2;" : "=f"(lo), "=f"(hi) : "l"(v));
}

__global__ void zero_state_kernel(){
    int idx = blockIdx.x*blockDim.x + threadIdx.x;
    if (idx < Bsz*HC*HW){ g_h[0][idx]=0.f; g_c[0][idx]=0.f; }
}

// ---------------- encoder conv1: 1 -> 8, 3x3, pad 1, relu ----------------
__global__ void enc1_kernel(const float* __restrict__ x,
                            const float* __restrict__ w,
                            const float* __restrict__ b){
    __shared__ float tile[10*34];
    __shared__ float ws[72];
    __shared__ float bs[8];
    int f   = blockIdx.z;                  // frame (b*T+t), 0..95
    int tid = threadIdx.y*32 + threadIdx.x;
    if (tid < 72) ws[tid] = w[tid];
    if (tid < 8)  bs[tid] = b[tid];
    const float* xin = x + (size_t)f*HW;
    int by0 = blockIdx.y*8, bx0 = blockIdx.x*32;
    for (int i = tid; i < 340; i += 256){
        int ly = i/34, lx = i%34;
        int gy = by0 + ly - 1, gx = bx0 + lx - 1;
        float v = 0.f;
        if (gy>=0 && gy<Hh && gx>=0 && gx<Ww) v = xin[gy*Ww+gx];
        tile[i] = v;
    }
    __syncthreads();
    float acc[8];
    #pragma unroll
    for (int o=0;o<8;o++) acc[o]=bs[o];
    int base = threadIdx.y*34 + threadIdx.x;
    #pragma unroll
    for (int k=0;k<9;k++){
        float v = tile[base + (k/3)*34 + (k%3)];
        #pragma unroll
        for (int o=0;o<8;o++) acc[o] = fmaf(ws[o*9+k], v, acc[o]);
    }
    int gy = by0 + threadIdx.y, gx = bx0 + threadIdx.x;
    float* outp = g_e1 + (size_t)f*EC*HW + gy*Ww + gx;
    #pragma unroll
    for (int o=0;o<8;o++) outp[(size_t)o*HW] = fmaxf(acc[o], 0.f);
}

// ---------------- encoder conv2: 8 -> 8, 3x3, pad 1, relu ----------------
__global__ void enc2_kernel(const float* __restrict__ w,
                            const float* __restrict__ b){
    __shared__ float tile[8*10*34];                 // 2720 floats
    __shared__ __align__(16) float ws[8*9*8];       // [cin][k][o]
    __shared__ float bs[8];
    int f   = blockIdx.z;
    int tid = threadIdx.y*32 + threadIdx.x;
    for (int i=tid; i<576; i+=256){
        int o = i & 7; int k = (i>>3)%9; int cin = i/72;
        ws[i] = w[(o*8+cin)*9 + k];
    }
    if (tid<8) bs[tid] = b[tid];
    const float* in = g_e1 + (size_t)f*EC*HW;
    int by0 = blockIdx.y*8, bx0 = blockIdx.x*32;
    for (int i=tid; i<8*340; i+=256){
        int c = i/340, rem = i%340;
        int ly = rem/34, lx = rem%34;
        int gy = by0+ly-1, gx = bx0+lx-1;
        tile[i] = (gy>=0 && gy<Hh && gx>=0 && gx<Ww) ? in[(size_t)c*HW + gy*Ww+gx] : 0.f;
    }
    __syncthreads();
    float acc[8];
    #pragma unroll
    for (int o=0;o<8;o++) acc[o]=bs[o];
    int base = threadIdx.y*34 + threadIdx.x;
    #pragma unroll
    for (int cin=0;cin<8;cin++){
        #pragma unroll
        for (int k=0;k<9;k++){
            float v = tile[cin*340 + base + (k/3)*34 + (k%3)];
            const float4* wp = (const float4*)(ws + (cin*9+k)*8);
            float4 w0 = wp[0], w1 = wp[1];
            acc[0]=fmaf(w0.x,v,acc[0]); acc[1]=fmaf(w0.y,v,acc[1]);
            acc[2]=fmaf(w0.z,v,acc[2]); acc[3]=fmaf(w0.w,v,acc[3]);
            acc[4]=fmaf(w1.x,v,acc[4]); acc[5]=fmaf(w1.y,v,acc[5]);
            acc[6]=fmaf(w1.z,v,acc[6]); acc[7]=fmaf(w1.w,v,acc[7]);
        }
    }
    int gy = by0+threadIdx.y, gx = bx0+threadIdx.x;
    float* outp = g_enc + (size_t)f*EC*HW + gy*Ww + gx;
    #pragma unroll
    for (int o=0;o<8;o++) outp[(size_t)o*HW] = fmaxf(acc[o], 0.f);
}

// ---------------- ConvLSTM step: conv(cat(enc_t,h), 24 -> 64) + gates ----
// blockIdx.z = b*4 + hcg ; thread computes 4 rows x (4 hc x 4 gates).
// Input tile stored DUPLICATED as float2{v,v} in dynamic smem so the f32x2
// broadcast operand comes from a single ld.shared.b64 (no MOV packs).
// launch_bounds(128,3): up to 170 regs for load-ahead; smem 72.6KB -> 3 blk/SM.
#define LSTM_TILE_F2   (12*18*34)                 // 7344 float2
#define LSTM_WS_FLOATS (24*9*16)                  // 3456 floats
#define LSTM_SMEM_BYTES (LSTM_TILE_F2*8 + LSTM_WS_FLOATS*4 + 64)

__global__ __launch_bounds__(128, 3)
void lstm_step_kernel(const float* __restrict__ cell_w,
                      const float* __restrict__ cell_b,
                      int t, int src){
    extern __shared__ float dsm[];
    float2* tile2 = (float2*)dsm;                  // duplicated input tile
    float*  ws    = dsm + LSTM_TILE_F2*2;          // [cin][k][o_l]
    float*  bs    = ws + LSTM_WS_FLOATS;

    int bz  = blockIdx.z;
    int b   = bz >> 2, hcg = bz & 3;
    int tx  = threadIdx.x, ty = threadIdx.y;
    int tid = ty*32 + tx;

    for (int i = tid; i < LSTM_WS_FLOATS; i += 128){
        int o_l = i & 15;
        int k   = (i >> 4) % 9;
        int cin = i / 144;
        int row = (o_l>>2)*16 + hcg*4 + (o_l&3);     // gate*16 + hc
        ws[i] = cell_w[(row*24 + cin)*9 + k];
    }
    if (tid < 16) bs[tid] = cell_b[(tid>>2)*16 + hcg*4 + (tid&3)];

    const float* enc_t = g_enc + (size_t)((b*Tt + t)*EC)*HW;
    const float* h_src = g_h[src] + (size_t)b*HC*HW;
    int by0 = blockIdx.y*16, bx0 = blockIdx.x*32;

    // acc[j][p]: lane pair = output channels (2j, 2j+1), p = pixel row 0..3
    unsigned long long acc[8][4];
    #pragma unroll
    for (int j=0;j<8;j++)
        #pragma unroll
        for (int p=0;p<4;p++) acc[j][p]=0ULL;

    #pragma unroll
    for (int phase=0; phase<2; phase++){
        __syncthreads();            // phase 1: wait until all reads of tile done
        for (int i = tid; i < 12*612; i += 128){
            int cl = i / 612, rem = i % 612;
            int ly = rem / 34, lx = rem % 34;
            int c  = cl + phase*12;
            int gy = by0 + ly - 1, gx = bx0 + lx - 1;
            float v = 0.f;
            if (gy>=0 && gy<Hh && gx>=0 && gx<Ww){
                v = (c < EC) ? enc_t[(size_t)c*HW + gy*Ww + gx]
                             : h_src[(size_t)(c-EC)*HW + gy*Ww + gx];
            }
            tile2[i] = make_float2(v, v);
        }
        __syncthreads();

        const unsigned long long* tbase =
            (const unsigned long long*)(tile2 + ty*4*34 + tx);
        #pragma unroll 1
        for (int cl=0; cl<12; cl++){
            const unsigned long long* tp = tbase + cl*612;
            const ulonglong2* wp = (const ulonglong2*)(ws + (size_t)(phase*12 + cl)*144);
            #pragma unroll
            for (int k=0;k<9;k++){
                const int r = k/3, c = k%3;
                ulonglong2 wA = wp[k*4+0];   // pairs (o0,o1),(o2,o3)
                ulonglong2 wB = wp[k*4+1];   // pairs (o4,o5),(o6,o7)
                ulonglong2 wC = wp[k*4+2];   // pairs (o8,o9),(o10,o11)
                ulonglong2 wD = wp[k*4+3];   // pairs (o12,o13),(o14,o15)
                unsigned long long vv0 = tp[(r+0)*34 + c];
                unsigned long long vv1 = tp[(r+1)*34 + c];
                unsigned long long vv2 = tp[(r+2)*34 + c];
                unsigned long long vv3 = tp[(r+3)*34 + c];
                #define STEP8(P, V) \
                    fma2(acc[0][P], V, wA.x); fma2(acc[1][P], V, wA.y); \
                    fma2(acc[2][P], V, wB.x); fma2(acc[3][P], V, wB.y); \
                    fma2(acc[4][P], V, wC.x); fma2(acc[5][P], V, wC.y); \
                    fma2(acc[6][P], V, wD.x); fma2(acc[7][P], V, wD.y);
                STEP8(0, vv0)
                STEP8(1, vv1)
                STEP8(2, vv2)
                STEP8(3, vv3)
                #undef STEP8
            }
        }
    }

    int gx  = bx0 + tx;
    int dst = src ^ 1;
    const float* c_src_p = g_c[src] + (size_t)b*HC*HW;
    float*       c_dst_p = g_c[dst] + (size_t)b*HC*HW;
    float*       h_dst_p = g_h[dst] + (size_t)b*HC*HW;
    #pragma unroll
    for (int p=0;p<4;p++){
        int gy = by0 + ty*4 + p;
        int pi = gy*Ww + gx;
        float g16[16];
        #pragma unroll
        for (int j=0;j<8;j++) unpack2(acc[j][p], g16[2*j], g16[2*j+1]);
        #pragma unroll
        for (int l=0;l<4;l++){
            int hc = hcg*4 + l;
            float ig = sigmf(g16[l]    + bs[l]);
            float fg = sigmf(g16[4+l]  + bs[4+l]);
            float og = sigmf(g16[8+l]  + bs[8+l]);
            float gg = tanhf(g16[12+l] + bs[12+l]);
            float cp = c_src_p[(size_t)hc*HW + pi];
            float cn = fg*cp + ig*gg;
            c_dst_p[(size_t)hc*HW + pi] = cn;
            h_dst_p[(size_t)hc*HW + pi] = og * tanhf(cn);
        }
    }
}

// ---------------- fused epilogue: mean/wp/gate/head/sigmoid --------------
__global__ void fuse_kernel(const float* __restrict__ sat, const int* __restrict__ months,
                            const float* __restrict__ wp_w, const float* __restrict__ wp_b,
                            const float* __restrict__ head_w, const float* __restrict__ head_b,
                            const float* __restrict__ sg_w1, const float* __restrict__ sg_b1,
                            const float* __restrict__ sg_w2, const float* __restrict__ sg_b2,
                            float* __restrict__ out){
    int idx = blockIdx.x*blockDim.x + threadIdx.x;
    if (idx >= Bsz*HW) return;
    int b = idx / HW, p = idx % HW;

    // scalar sat gate (1->8->1 MLP) + month prior
    float s = sat[b];
    float pre = sg_b2[0];
    #pragma unroll
    for (int j=0;j<8;j++){
        float hid = fmaxf(fmaf(sg_w1[j], s, sg_b1[j]), 0.f);
        pre = fmaf(sg_w2[j], hid, pre);
    }
    int m = months[b];
    float prior = (m>=3 && m<=6) ? 0.6f : 0.3f;
    float alpha = prior * sigmf(pre);

    // temporal mean of encoder features
    float feat[8];
    #pragma unroll
    for (int c=0;c<8;c++){
        float a = 0.f;
        #pragma unroll
        for (int t=0;t<Tt;t++) a += g_enc[(size_t)((b*Tt+t)*EC+c)*HW + p];
        feat[c] = a * (1.0f/12.0f);
    }

    // wp 1x1 conv + fuse + head 1x1 conv + sigmoid
    float res = head_b[0];
    #pragma unroll
    for (int hc=0; hc<16; hc++){
        float haux = wp_b[hc];
        #pragma unroll
        for (int c=0;c<8;c++) haux = fmaf(wp_w[hc*8+c], feat[c], haux);
        float hm = g_h[0][(size_t)(b*HC+hc)*HW + p];   // after 12 steps h lives in buf 0
        res = fmaf(head_w[hc], hm + alpha*haux, res);
    }
    out[idx] = sigmf(res);
}

extern "C" void kernel_launch(void* const* d_in, const int* in_sizes, int n_in,
                              void* d_out, int out_size){
    const float* x       = (const float*)d_in[0];
    const float* sat     = (const float*)d_in[1];
    const int*   months  = (const int*)  d_in[2];
    const float* enc_w1  = (const float*)d_in[3];
    const float* enc_b1  = (const float*)d_in[4];
    const float* enc_w2  = (const float*)d_in[5];
    const float* enc_b2  = (const float*)d_in[6];
    const float* cell_w  = (const float*)d_in[7];
    const float* cell_b  = (const float*)d_in[8];
    const float* wp_w    = (const float*)d_in[9];
    const float* wp_b    = (const float*)d_in[10];
    const float* head_w  = (const float*)d_in[11];
    const float* head_b  = (const float*)d_in[12];
    const float* sg_w1   = (const float*)d_in[13];
    const float* sg_b1   = (const float*)d_in[14];
    const float* sg_w2   = (const float*)d_in[15];
    const float* sg_b2   = (const float*)d_in[16];
    float* out = (float*)d_out;

    // opt-in to >48KB dynamic smem (host-side attribute set; capture-safe)
    cudaFuncSetAttribute(lstm_step_kernel,
                         cudaFuncAttributeMaxDynamicSharedMemorySize,
                         LSTM_SMEM_BYTES);

    dim3 blk256(32, 8);
    zero_state_kernel<<<(Bsz*HC*HW + 255)/256, 256>>>();
    enc1_kernel<<<dim3(8, 32, Bsz*Tt), blk256>>>(x, enc_w1, enc_b1);
    enc2_kernel<<<dim3(8, 32, Bsz*Tt), blk256>>>(enc_w2, enc_b2);
    for (int t=0; t<Tt; t++){
        // src parity: t even reads buf0, writes buf1; final h lands in buf0
        lstm_step_kernel<<<dim3(8, 16, Bsz*4), dim3(32,4), LSTM_SMEM_BYTES>>>(cell_w, cell_b, t, t & 1);
    }
    fuse_kernel<<<(Bsz*HW + 255)/256, 256>>>(sat, months, wp_w, wp_b,
                                             head_w, head_b, sg_w1, sg_b1,
                                             sg_w2, sg_b2, out);
}

// round 8
// speedup vs baseline: 1.2400x; 1.2400x over previous
#include <cuda_runtime.h>
#include <math.h>

#define Bsz 8
#define Tt 12
#define Hh 256
#define Ww 256
#define EC 8
#define HC 16
#define HW (Hh*Ww)

// Scratch (device globals; no allocations allowed)
__device__ float g_e1 [Bsz*Tt*EC*HW];   // encoder conv1 output (96 frames x 8ch)
__device__ float g_enc[Bsz*Tt*EC*HW];   // encoder conv2 output
__device__ float g_h[2][Bsz*HC*HW];     // ping-pong hidden state
__device__ float g_c[2][Bsz*HC*HW];     // ping-pong cell state

__device__ __forceinline__ float sigmf(float x){ return 1.0f/(1.0f+expf(-x)); }

// ---- packed f32x2 helpers (sm_100+) ----
__device__ __forceinline__ void fma2(unsigned long long& acc,
                                     unsigned long long a,
                                     unsigned long long b){
    asm("fma.rn.f32x2 %0, %1, %2, %3;" : "=l"(acc) : "l"(a), "l"(b), "l"(acc));
}
__device__ __forceinline__ void unpack2(unsigned long long v, float& lo, float& hi){
    asm("mov.b64 {%0, %1}, %2;" : "=f"(lo), "=f"(hi) : "l"(v));
}

__global__ void zero_state_kernel(){
    int idx = blockIdx.x*blockDim.x + threadIdx.x;
    if (idx < Bsz*HC*HW){ g_h[0][idx]=0.f; g_c[0][idx]=0.f; }
}

// ---------------- encoder conv1: 1 -> 8, 3x3, pad 1, relu ----------------
__global__ void enc1_kernel(const float* __restrict__ x,
                            const float* __restrict__ w,
                            const float* __restrict__ b){
    __shared__ float tile[10*34];
    __shared__ float ws[72];
    __shared__ float bs[8];
    int f   = blockIdx.z;                  // frame (b*T+t), 0..95
    int tid = threadIdx.y*32 + threadIdx.x;
    if (tid < 72) ws[tid] = w[tid];
    if (tid < 8)  bs[tid] = b[tid];
    const float* xin = x + (size_t)f*HW;
    int by0 = blockIdx.y*8, bx0 = blockIdx.x*32;
    for (int i = tid; i < 340; i += 256){
        int ly = i/34, lx = i%34;
        int gy = by0 + ly - 1, gx = bx0 + lx - 1;
        float v = 0.f;
        if (gy>=0 && gy<Hh && gx>=0 && gx<Ww) v = xin[gy*Ww+gx];
        tile[i] = v;
    }
    __syncthreads();
    float acc[8];
    #pragma unroll
    for (int o=0;o<8;o++) acc[o]=bs[o];
    int base = threadIdx.y*34 + threadIdx.x;
    #pragma unroll
    for (int k=0;k<9;k++){
        float v = tile[base + (k/3)*34 + (k%3)];
        #pragma unroll
        for (int o=0;o<8;o++) acc[o] = fmaf(ws[o*9+k], v, acc[o]);
    }
    int gy = by0 + threadIdx.y, gx = bx0 + threadIdx.x;
    float* outp = g_e1 + (size_t)f*EC*HW + gy*Ww + gx;
    #pragma unroll
    for (int o=0;o<8;o++) outp[(size_t)o*HW] = fmaxf(acc[o], 0.f);
}

// ---------------- encoder conv2: 8 -> 8, 3x3, pad 1, relu ----------------
__global__ void enc2_kernel(const float* __restrict__ w,
                            const float* __restrict__ b){
    __shared__ float tile[8*10*34];                 // 2720 floats
    __shared__ __align__(16) float ws[8*9*8];       // [cin][k][o]
    __shared__ float bs[8];
    int f   = blockIdx.z;
    int tid = threadIdx.y*32 + threadIdx.x;
    for (int i=tid; i<576; i+=256){
        int o = i & 7; int k = (i>>3)%9; int cin = i/72;
        ws[i] = w[(o*8+cin)*9 + k];
    }
    if (tid<8) bs[tid] = b[tid];
    const float* in = g_e1 + (size_t)f*EC*HW;
    int by0 = blockIdx.y*8, bx0 = blockIdx.x*32;
    for (int i=tid; i<8*340; i+=256){
        int c = i/340, rem = i%340;
        int ly = rem/34, lx = rem%34;
        int gy = by0+ly-1, gx = bx0+lx-1;
        tile[i] = (gy>=0 && gy<Hh && gx>=0 && gx<Ww) ? in[(size_t)c*HW + gy*Ww+gx] : 0.f;
    }
    __syncthreads();
    float acc[8];
    #pragma unroll
    for (int o=0;o<8;o++) acc[o]=bs[o];
    int base = threadIdx.y*34 + threadIdx.x;
    #pragma unroll
    for (int cin=0;cin<8;cin++){
        #pragma unroll
        for (int k=0;k<9;k++){
            float v = tile[cin*340 + base + (k/3)*34 + (k%3)];
            const float4* wp = (const float4*)(ws + (cin*9+k)*8);
            float4 w0 = wp[0], w1 = wp[1];
            acc[0]=fmaf(w0.x,v,acc[0]); acc[1]=fmaf(w0.y,v,acc[1]);
            acc[2]=fmaf(w0.z,v,acc[2]); acc[3]=fmaf(w0.w,v,acc[3]);
            acc[4]=fmaf(w1.x,v,acc[4]); acc[5]=fmaf(w1.y,v,acc[5]);
            acc[6]=fmaf(w1.z,v,acc[6]); acc[7]=fmaf(w1.w,v,acc[7]);
        }
    }
    int gy = by0+threadIdx.y, gx = bx0+threadIdx.x;
    float* outp = g_enc + (size_t)f*EC*HW + gy*Ww + gx;
    #pragma unroll
    for (int o=0;o<8;o++) outp[(size_t)o*HW] = fmaxf(acc[o], 0.f);
}

// ---------------- ConvLSTM step: conv(cat(enc_t,h), 24 -> 64) + gates ----
// blockIdx.z = b*4 + hcg ; thread computes 4 rows x (4 hc x 4 gates).
// f32x2 math; tile stored DUPLICATED as float2{v,v} so the broadcast operand
// is a single LDS.64 (no MOV packs). 6 input channels per phase x 4 phases
// keeps static smem at 43.3KB -> 4 blocks/SM (16 warps) like R5.
__global__ __launch_bounds__(128, 4)
void lstm_step_kernel(const float* __restrict__ cell_w,
                      const float* __restrict__ cell_b,
                      int t, int src){
    __shared__ float2 tile2[6*18*34];                // 3672 float2 = 29.4KB
    __shared__ __align__(16) float ws[24*9*16];      // [cin][k][o_l], 13.8KB
    __shared__ float bs[16];
    int bz  = blockIdx.z;
    int b   = bz >> 2, hcg = bz & 3;
    int tx  = threadIdx.x, ty = threadIdx.y;
    int tid = ty*32 + tx;

    for (int i = tid; i < 3456; i += 128){
        int o_l = i & 15;
        int k   = (i >> 4) % 9;
        int cin = i / 144;
        int row = (o_l>>2)*16 + hcg*4 + (o_l&3);     // gate*16 + hc
        ws[i] = cell_w[(row*24 + cin)*9 + k];
    }
    if (tid < 16) bs[tid] = cell_b[(tid>>2)*16 + hcg*4 + (tid&3)];

    const float* enc_t = g_enc + (size_t)((b*Tt + t)*EC)*HW;
    const float* h_src = g_h[src] + (size_t)b*HC*HW;
    int by0 = blockIdx.y*16, bx0 = blockIdx.x*32;

    // acc[j][p]: lane pair = output channels (2j, 2j+1), p = pixel row 0..3
    unsigned long long acc[8][4];
    #pragma unroll
    for (int j=0;j<8;j++)
        #pragma unroll
        for (int p=0;p<4;p++) acc[j][p]=0ULL;

    #pragma unroll
    for (int phase=0; phase<4; phase++){
        __syncthreads();            // wait until all reads of prior tile done
        for (int i = tid; i < 6*612; i += 128){
            int cl = i / 612, rem = i % 612;
            int ly = rem / 34, lx = rem % 34;
            int c  = cl + phase*6;
            int gy = by0 + ly - 1, gx = bx0 + lx - 1;
            float v = 0.f;
            if (gy>=0 && gy<Hh && gx>=0 && gx<Ww){
                v = (c < EC) ? enc_t[(size_t)c*HW + gy*Ww + gx]
                             : h_src[(size_t)(c-EC)*HW + gy*Ww + gx];
            }
            tile2[i] = make_float2(v, v);
        }
        __syncthreads();

        const unsigned long long* tbase =
            (const unsigned long long*)(tile2 + ty*4*34 + tx);
        #pragma unroll 1
        for (int cl=0; cl<6; cl++){
            const unsigned long long* tp = tbase + cl*612;
            const ulonglong2* wp = (const ulonglong2*)(ws + (size_t)(phase*6 + cl)*144);
            #pragma unroll
            for (int k=0;k<9;k++){
                const int r = k/3, c = k%3;
                ulonglong2 wA = wp[k*4+0];   // pairs (o0,o1),(o2,o3)
                ulonglong2 wB = wp[k*4+1];   // pairs (o4,o5),(o6,o7)
                ulonglong2 wC = wp[k*4+2];   // pairs (o8,o9),(o10,o11)
                ulonglong2 wD = wp[k*4+3];   // pairs (o12,o13),(o14,o15)
                unsigned long long vv0 = tp[(r+0)*34 + c];
                unsigned long long vv1 = tp[(r+1)*34 + c];
                unsigned long long vv2 = tp[(r+2)*34 + c];
                unsigned long long vv3 = tp[(r+3)*34 + c];
                #define STEP8(P, V) \
                    fma2(acc[0][P], V, wA.x); fma2(acc[1][P], V, wA.y); \
                    fma2(acc[2][P], V, wB.x); fma2(acc[3][P], V, wB.y); \
                    fma2(acc[4][P], V, wC.x); fma2(acc[5][P], V, wC.y); \
                    fma2(acc[6][P], V, wD.x); fma2(acc[7][P], V, wD.y);
                STEP8(0, vv0)
                STEP8(1, vv1)
                STEP8(2, vv2)
                STEP8(3, vv3)
                #undef STEP8
            }
        }
    }

    int gx  = bx0 + tx;
    int dst = src ^ 1;
    const float* c_src_p = g_c[src] + (size_t)b*HC*HW;
    float*       c_dst_p = g_c[dst] + (size_t)b*HC*HW;
    float*       h_dst_p = g_h[dst] + (size_t)b*HC*HW;
    #pragma unroll
    for (int p=0;p<4;p++){
        int gy = by0 + ty*4 + p;
        int pi = gy*Ww + gx;
        float g16[16];
        #pragma unroll
        for (int j=0;j<8;j++) unpack2(acc[j][p], g16[2*j], g16[2*j+1]);
        #pragma unroll
        for (int l=0;l<4;l++){
            int hc = hcg*4 + l;
            float ig = sigmf(g16[l]    + bs[l]);
            float fg = sigmf(g16[4+l]  + bs[4+l]);
            float og = sigmf(g16[8+l]  + bs[8+l]);
            float gg = tanhf(g16[12+l] + bs[12+l]);
            float cp = c_src_p[(size_t)hc*HW + pi];
            float cn = fg*cp + ig*gg;
            c_dst_p[(size_t)hc*HW + pi] = cn;
            h_dst_p[(size_t)hc*HW + pi] = og * tanhf(cn);
        }
    }
}

// ---------------- fused epilogue: mean/wp/gate/head/sigmoid --------------
__global__ void fuse_kernel(const float* __restrict__ sat, const int* __restrict__ months,
                            const float* __restrict__ wp_w, const float* __restrict__ wp_b,
                            const float* __restrict__ head_w, const float* __restrict__ head_b,
                            const float* __restrict__ sg_w1, const float* __restrict__ sg_b1,
                            const float* __restrict__ sg_w2, const float* __restrict__ sg_b2,
                            float* __restrict__ out){
    int idx = blockIdx.x*blockDim.x + threadIdx.x;
    if (idx >= Bsz*HW) return;
    int b = idx / HW, p = idx % HW;

    // scalar sat gate (1->8->1 MLP) + month prior
    float s = sat[b];
    float pre = sg_b2[0];
    #pragma unroll
    for (int j=0;j<8;j++){
        float hid = fmaxf(fmaf(sg_w1[j], s, sg_b1[j]), 0.f);
        pre = fmaf(sg_w2[j], hid, pre);
    }
    int m = months[b];
    float prior = (m>=3 && m<=6) ? 0.6f : 0.3f;
    float alpha = prior * sigmf(pre);

    // temporal mean of encoder features
    float feat[8];
    #pragma unroll
    for (int c=0;c<8;c++){
        float a = 0.f;
        #pragma unroll
        for (int t=0;t<Tt;t++) a += g_enc[(size_t)((b*Tt+t)*EC+c)*HW + p];
        feat[c] = a * (1.0f/12.0f);
    }

    // wp 1x1 conv + fuse + head 1x1 conv + sigmoid
    float res = head_b[0];
    #pragma unroll
    for (int hc=0; hc<16; hc++){
        float haux = wp_b[hc];
        #pragma unroll
        for (int c=0;c<8;c++) haux = fmaf(wp_w[hc*8+c], feat[c], haux);
        float hm = g_h[0][(size_t)(b*HC+hc)*HW + p];   // after 12 steps h lives in buf 0
        res = fmaf(head_w[hc], hm + alpha*haux, res);
    }
    out[idx] = sigmf(res);
}

extern "C" void kernel_launch(void* const* d_in, const int* in_sizes, int n_in,
                              void* d_out, int out_size){
    const float* x       = (const float*)d_in[0];
    const float* sat     = (const float*)d_in[1];
    const int*   months  = (const int*)  d_in[2];
    const float* enc_w1  = (const float*)d_in[3];
    const float* enc_b1  = (const float*)d_in[4];
    const float* enc_w2  = (const float*)d_in[5];
    const float* enc_b2  = (const float*)d_in[6];
    const float* cell_w  = (const float*)d_in[7];
    const float* cell_b  = (const float*)d_in[8];
    const float* wp_w    = (const float*)d_in[9];
    const float* wp_b    = (const float*)d_in[10];
    const float* head_w  = (const float*)d_in[11];
    const float* head_b  = (const float*)d_in[12];
    const float* sg_w1   = (const float*)d_in[13];
    const float* sg_b1   = (const float*)d_in[14];
    const float* sg_w2   = (const float*)d_in[15];
    const float* sg_b2   = (const float*)d_in[16];
    float* out = (float*)d_out;

    dim3 blk256(32, 8);
    zero_state_kernel<<<(Bsz*HC*HW + 255)/256, 256>>>();
    enc1_kernel<<<dim3(8, 32, Bsz*Tt), blk256>>>(x, enc_w1, enc_b1);
    enc2_kernel<<<dim3(8, 32, Bsz*Tt), blk256>>>(enc_w2, enc_b2);
    for (int t=0; t<Tt; t++){
        // src parity: t even reads buf0, writes buf1; final h lands in buf0
        lstm_step_kernel<<<dim3(8, 16, Bsz*4), dim3(32,4)>>>(cell_w, cell_b, t, t & 1);
    }
    fuse_kernel<<<(Bsz*HW + 255)/256, 256>>>(sat, months, wp_w, wp_b,
                                             head_w, head_b, sg_w1, sg_b1,
                                             sg_w2, sg_b2, out);
}

// round 9
// speedup vs baseline: 1.4462x; 1.1663x over previous
#include <cuda_runtime.h>
#include <math.h>

#define Bsz 8
#define Tt 12
#define Hh 256
#define Ww 256
#define EC 8
#define HC 16
#define HW (Hh*Ww)

// Scratch (device globals; no allocations allowed)
__device__ float g_e1 [Bsz*Tt*EC*HW];   // encoder conv1 output (96 frames x 8ch)
__device__ float g_enc[Bsz*Tt*EC*HW];   // encoder conv2 output
__device__ float g_h[2][Bsz*HC*HW];     // ping-pong hidden state
__device__ float g_c[2][Bsz*HC*HW];     // ping-pong cell state

__device__ __forceinline__ float sigmf(float x){ return 1.0f/(1.0f+expf(-x)); }

// ---- packed f32x2 helpers (sm_100+) ----
__device__ __forceinline__ void fma2(unsigned long long& acc,
                                     unsigned long long a,
                                     unsigned long long b){
    asm("fma.rn.f32x2 %0, %1, %2, %3;" : "=l"(acc) : "l"(a), "l"(b), "l"(acc));
}
__device__ __forceinline__ unsigned long long pack2(float v){
    unsigned long long r;
    asm("mov.b64 %0, {%1, %1};" : "=l"(r) : "f"(v));
    return r;
}
__device__ __forceinline__ void unpack2(unsigned long long v, float& lo, float& hi){
    asm("mov.b64 {%0, %1}, %2;" : "=f"(lo), "=f"(hi) : "l"(v));
}

__global__ void zero_state_kernel(){
    int idx = blockIdx.x*blockDim.x + threadIdx.x;
    if (idx < Bsz*HC*HW){ g_h[0][idx]=0.f; g_c[0][idx]=0.f; }
}

// ---------------- encoder conv1: 1 -> 8, 3x3, pad 1, relu ----------------
__global__ void enc1_kernel(const float* __restrict__ x,
                            const float* __restrict__ w,
                            const float* __restrict__ b){
    __shared__ float tile[10*34];
    __shared__ float ws[72];
    __shared__ float bs[8];
    int f   = blockIdx.z;                  // frame (b*T+t), 0..95
    int tid = threadIdx.y*32 + threadIdx.x;
    if (tid < 72) ws[tid] = w[tid];
    if (tid < 8)  bs[tid] = b[tid];
    const float* xin = x + (size_t)f*HW;
    int by0 = blockIdx.y*8, bx0 = blockIdx.x*32;
    for (int i = tid; i < 340; i += 256){
        int ly = i/34, lx = i%34;
        int gy = by0 + ly - 1, gx = bx0 + lx - 1;
        float v = 0.f;
        if (gy>=0 && gy<Hh && gx>=0 && gx<Ww) v = xin[gy*Ww+gx];
        tile[i] = v;
    }
    __syncthreads();
    float acc[8];
    #pragma unroll
    for (int o=0;o<8;o++) acc[o]=bs[o];
    int base = threadIdx.y*34 + threadIdx.x;
    #pragma unroll
    for (int k=0;k<9;k++){
        float v = tile[base + (k/3)*34 + (k%3)];
        #pragma unroll
        for (int o=0;o<8;o++) acc[o] = fmaf(ws[o*9+k], v, acc[o]);
    }
    int gy = by0 + threadIdx.y, gx = bx0 + threadIdx.x;
    float* outp = g_e1 + (size_t)f*EC*HW + gy*Ww + gx;
    #pragma unroll
    for (int o=0;o<8;o++) outp[(size_t)o*HW] = fmaxf(acc[o], 0.f);
}

// ---------------- encoder conv2: 8 -> 8, 3x3, pad 1, relu ----------------
__global__ void enc2_kernel(const float* __restrict__ w,
                            const float* __restrict__ b){
    __shared__ float tile[8*10*34];                 // 2720 floats
    __shared__ __align__(16) float ws[8*9*8];       // [cin][k][o]
    __shared__ float bs[8];
    int f   = blockIdx.z;
    int tid = threadIdx.y*32 + threadIdx.x;
    for (int i=tid; i<576; i+=256){
        int o = i & 7; int k = (i>>3)%9; int cin = i/72;
        ws[i] = w[(o*8+cin)*9 + k];
    }
    if (tid<8) bs[tid] = b[tid];
    const float* in = g_e1 + (size_t)f*EC*HW;
    int by0 = blockIdx.y*8, bx0 = blockIdx.x*32;
    for (int i=tid; i<8*340; i+=256){
        int c = i/340, rem = i%340;
        int ly = rem/34, lx = rem%34;
        int gy = by0+ly-1, gx = bx0+lx-1;
        tile[i] = (gy>=0 && gy<Hh && gx>=0 && gx<Ww) ? in[(size_t)c*HW + gy*Ww+gx] : 0.f;
    }
    __syncthreads();
    float acc[8];
    #pragma unroll
    for (int o=0;o<8;o++) acc[o]=bs[o];
    int base = threadIdx.y*34 + threadIdx.x;
    #pragma unroll
    for (int cin=0;cin<8;cin++){
        #pragma unroll
        for (int k=0;k<9;k++){
            float v = tile[cin*340 + base + (k/3)*34 + (k%3)];
            const float4* wp = (const float4*)(ws + (cin*9+k)*8);
            float4 w0 = wp[0], w1 = wp[1];
            acc[0]=fmaf(w0.x,v,acc[0]); acc[1]=fmaf(w0.y,v,acc[1]);
            acc[2]=fmaf(w0.z,v,acc[2]); acc[3]=fmaf(w0.w,v,acc[3]);
            acc[4]=fmaf(w1.x,v,acc[4]); acc[5]=fmaf(w1.y,v,acc[5]);
            acc[6]=fmaf(w1.z,v,acc[6]); acc[7]=fmaf(w1.w,v,acc[7]);
        }
    }
    int gy = by0+threadIdx.y, gx = bx0+threadIdx.x;
    float* outp = g_enc + (size_t)f*EC*HW + gy*Ww + gx;
    #pragma unroll
    for (int o=0;o<8;o++) outp[(size_t)o*HW] = fmaxf(acc[o], 0.f);
}

// ---------------- ConvLSTM step: conv(cat(enc_t,h), 24 -> 64) + gates ----
// blockIdx.z = b*4 + hcg ; 256 threads, each computes 2 rows x (4hc x 4gates).
// Halved per-thread state -> ~64 regs -> 4 blocks/SM = 32 warps (2x R5 occ).
// f32x2 math; plain float tile (LDS.32 input + pack2 — packs proven ~free in
// R8 profile); 12 input channels per phase x 2 phases, 43.2KB static smem.
__global__ __launch_bounds__(256, 4)
void lstm_step_kernel(const float* __restrict__ cell_w,
                      const float* __restrict__ cell_b,
                      int t, int src){
    __shared__ float tile[12*18*34];                 // 7344 floats = 29.4KB
    __shared__ __align__(16) float ws[24*9*16];      // [cin][k][o_l], 13.8KB
    __shared__ float bs[16];
    int bz  = blockIdx.z;
    int b   = bz >> 2, hcg = bz & 3;
    int tx  = threadIdx.x, ty = threadIdx.y;
    int tid = ty*32 + tx;

    for (int i = tid; i < 3456; i += 256){
        int o_l = i & 15;
        int k   = (i >> 4) % 9;
        int cin = i / 144;
        int row = (o_l>>2)*16 + hcg*4 + (o_l&3);     // gate*16 + hc
        ws[i] = cell_w[(row*24 + cin)*9 + k];
    }
    if (tid < 16) bs[tid] = cell_b[(tid>>2)*16 + hcg*4 + (tid&3)];

    const float* enc_t = g_enc + (size_t)((b*Tt + t)*EC)*HW;
    const float* h_src = g_h[src] + (size_t)b*HC*HW;
    int by0 = blockIdx.y*16, bx0 = blockIdx.x*32;

    // acc[j][p]: lane pair = output channels (2j, 2j+1), p = pixel row 0..1
    unsigned long long acc[8][2];
    #pragma unroll
    for (int j=0;j<8;j++)
        #pragma unroll
        for (int p=0;p<2;p++) acc[j][p]=0ULL;

    #pragma unroll
    for (int phase=0; phase<2; phase++){
        __syncthreads();            // wait until all reads of prior tile done
        for (int i = tid; i < 12*612; i += 256){
            int cl = i / 612, rem = i % 612;
            int ly = rem / 34, lx = rem % 34;
            int c  = cl + phase*12;
            int gy = by0 + ly - 1, gx = bx0 + lx - 1;
            float v = 0.f;
            if (gy>=0 && gy<Hh && gx>=0 && gx<Ww){
                v = (c < EC) ? enc_t[(size_t)c*HW + gy*Ww + gx]
                             : h_src[(size_t)(c-EC)*HW + gy*Ww + gx];
            }
            tile[i] = v;
        }
        __syncthreads();

        const float* tbase = tile + ty*2*34 + tx;
        #pragma unroll 1
        for (int cl=0; cl<12; cl++){
            const float*      tp = tbase + cl*612;
            const ulonglong2* wp = (const ulonglong2*)(ws + (size_t)(phase*12 + cl)*144);
            #pragma unroll
            for (int k=0;k<9;k++){
                const int r = k/3, c = k%3;
                ulonglong2 wA = wp[k*4+0];   // pairs (o0,o1),(o2,o3)
                ulonglong2 wB = wp[k*4+1];   // pairs (o4,o5),(o6,o7)
                ulonglong2 wC = wp[k*4+2];   // pairs (o8,o9),(o10,o11)
                ulonglong2 wD = wp[k*4+3];   // pairs (o12,o13),(o14,o15)
                unsigned long long vv0 = pack2(tp[(r+0)*34 + c]);
                unsigned long long vv1 = pack2(tp[(r+1)*34 + c]);
                #define STEP8(P, V) \
                    fma2(acc[0][P], V, wA.x); fma2(acc[1][P], V, wA.y); \
                    fma2(acc[2][P], V, wB.x); fma2(acc[3][P], V, wB.y); \
                    fma2(acc[4][P], V, wC.x); fma2(acc[5][P], V, wC.y); \
                    fma2(acc[6][P], V, wD.x); fma2(acc[7][P], V, wD.y);
                STEP8(0, vv0)
                STEP8(1, vv1)
                #undef STEP8
            }
        }
    }

    int gx  = bx0 + tx;
    int dst = src ^ 1;
    const float* c_src_p = g_c[src] + (size_t)b*HC*HW;
    float*       c_dst_p = g_c[dst] + (size_t)b*HC*HW;
    float*       h_dst_p = g_h[dst] + (size_t)b*HC*HW;
    #pragma unroll
    for (int p=0;p<2;p++){
        int gy = by0 + ty*2 + p;
        int pi = gy*Ww + gx;
        float g16[16];
        #pragma unroll
        for (int j=0;j<8;j++) unpack2(acc[j][p], g16[2*j], g16[2*j+1]);
        #pragma unroll
        for (int l=0;l<4;l++){
            int hc = hcg*4 + l;
            float ig = sigmf(g16[l]    + bs[l]);
            float fg = sigmf(g16[4+l]  + bs[4+l]);
            float og = sigmf(g16[8+l]  + bs[8+l]);
            float gg = tanhf(g16[12+l] + bs[12+l]);
            float cp = c_src_p[(size_t)hc*HW + pi];
            float cn = fg*cp + ig*gg;
            c_dst_p[(size_t)hc*HW + pi] = cn;
            h_dst_p[(size_t)hc*HW + pi] = og * tanhf(cn);
        }
    }
}

// ---------------- fused epilogue: mean/wp/gate/head/sigmoid --------------
__global__ void fuse_kernel(const float* __restrict__ sat, const int* __restrict__ months,
                            const float* __restrict__ wp_w, const float* __restrict__ wp_b,
                            const float* __restrict__ head_w, const float* __restrict__ head_b,
                            const float* __restrict__ sg_w1, const float* __restrict__ sg_b1,
                            const float* __restrict__ sg_w2, const float* __restrict__ sg_b2,
                            float* __restrict__ out){
    int idx = blockIdx.x*blockDim.x + threadIdx.x;
    if (idx >= Bsz*HW) return;
    int b = idx / HW, p = idx % HW;

    // scalar sat gate (1->8->1 MLP) + month prior
    float s = sat[b];
    float pre = sg_b2[0];
    #pragma unroll
    for (int j=0;j<8;j++){
        float hid = fmaxf(fmaf(sg_w1[j], s, sg_b1[j]), 0.f);
        pre = fmaf(sg_w2[j], hid, pre);
    }
    int m = months[b];
    float prior = (m>=3 && m<=6) ? 0.6f : 0.3f;
    float alpha = prior * sigmf(pre);

    // temporal mean of encoder features
    float feat[8];
    #pragma unroll
    for (int c=0;c<8;c++){
        float a = 0.f;
        #pragma unroll
        for (int t=0;t<Tt;t++) a += g_enc[(size_t)((b*Tt+t)*EC+c)*HW + p];
        feat[c] = a * (1.0f/12.0f);
    }

    // wp 1x1 conv + fuse + head 1x1 conv + sigmoid
    float res = head_b[0];
    #pragma unroll
    for (int hc=0; hc<16; hc++){
        float haux = wp_b[hc];
        #pragma unroll
        for (int c=0;c<8;c++) haux = fmaf(wp_w[hc*8+c], feat[c], haux);
        float hm = g_h[0][(size_t)(b*HC+hc)*HW + p];   // after 12 steps h lives in buf 0
        res = fmaf(head_w[hc], hm + alpha*haux, res);
    }
    out[idx] = sigmf(res);
}

extern "C" void kernel_launch(void* const* d_in, const int* in_sizes, int n_in,
                              void* d_out, int out_size){
    const float* x       = (const float*)d_in[0];
    const float* sat     = (const float*)d_in[1];
    const int*   months  = (const int*)  d_in[2];
    const float* enc_w1  = (const float*)d_in[3];
    const float* enc_b1  = (const float*)d_in[4];
    const float* enc_w2  = (const float*)d_in[5];
    const float* enc_b2  = (const float*)d_in[6];
    const float* cell_w  = (const float*)d_in[7];
    const float* cell_b  = (const float*)d_in[8];
    const float* wp_w    = (const float*)d_in[9];
    const float* wp_b    = (const float*)d_in[10];
    const float* head_w  = (const float*)d_in[11];
    const float* head_b  = (const float*)d_in[12];
    const float* sg_w1   = (const float*)d_in[13];
    const float* sg_b1   = (const float*)d_in[14];
    const float* sg_w2   = (const float*)d_in[15];
    const float* sg_b2   = (const float*)d_in[16];
    float* out = (float*)d_out;

    dim3 blk256(32, 8);
    zero_state_kernel<<<(Bsz*HC*HW + 255)/256, 256>>>();
    enc1_kernel<<<dim3(8, 32, Bsz*Tt), blk256>>>(x, enc_w1, enc_b1);
    enc2_kernel<<<dim3(8, 32, Bsz*Tt), blk256>>>(enc_w2, enc_b2);
    for (int t=0; t<Tt; t++){
        // src parity: t even reads buf0, writes buf1; final h lands in buf0
        lstm_step_kernel<<<dim3(8, 16, Bsz*4), dim3(32,8)>>>(cell_w, cell_b, t, t & 1);
    }
    fuse_kernel<<<(Bsz*HW + 255)/256, 256>>>(sat, months, wp_w, wp_b,
                                             head_w, head_b, sg_w1, sg_b1,
                                             sg_w2, sg_b2, out);
}